// round 6
// baseline (speedup 1.0000x reference)
#include <cuda_runtime.h>
#include <cuda_bf16.h>
#include <cstdint>

// ---------------------------------------------------------------------------
// SO3_Linear: out[b,m,o] = sum_i x[b,m,i] * W[l(m)][o][i]  (+ bias on m==0)
// B=20000, M=49, IN=OUT=128, LMAX=6 (7 weights)
//
// sm_103 BASE target (no tcgen05/TMA available in this toolchain): use
// warp-level mma.sync.m16n8k16 bf16 with fp32 accumulators, 3-pass bf16
// error compensation: Xh*Wh + Xh*Wl + Xl*Wh  (rel err ~2^-16).
// ---------------------------------------------------------------------------

#define B_TOTAL   20000
#define M_TOTAL   49
#define IN_DIM    128
#define OUT_DIM   128
#define TB        64                              // batch rows per CTA
#define NB_TILES  ((B_TOTAL + TB - 1) / TB)       // 313

#define PITCH     136                             // bf16 elems per smem row (272 B)

// SMEM byte offsets (all 16B aligned)
#define SMEM_XH   0
#define SMEM_XL   (SMEM_XH + TB * PITCH * 2)          // 17408
#define SMEM_WH   (SMEM_XL + TB * PITCH * 2)          // 34816
#define SMEM_WL   (SMEM_WH + OUT_DIM * PITCH * 2)     // 69632
#define SMEM_TOTAL (SMEM_WL + OUT_DIM * PITCH * 2)    // 104448

__device__ __forceinline__ uint32_t smem_u32(const void* p) {
    uint32_t a;
    asm("{ .reg .u64 t; cvta.to.shared.u64 t, %1; cvt.u32.u64 %0, t; }"
        : "=r"(a) : "l"(p));
    return a;
}

__device__ __forceinline__ uint32_t pack_bf16(__nv_bfloat16 a, __nv_bfloat16 b) {
    return (uint32_t)__bfloat16_as_ushort(a) | ((uint32_t)__bfloat16_as_ushort(b) << 16);
}

// Split two fp32 into (hi, lo) bf16x2 pairs: v = hi + lo + O(2^-17 |v|)
__device__ __forceinline__ void split2(float a, float b, uint32_t& h, uint32_t& l) {
    __nv_bfloat16 ah = __float2bfloat16_rn(a);
    __nv_bfloat16 bh = __float2bfloat16_rn(b);
    float ar = a - __bfloat162float(ah);
    float br = b - __bfloat162float(bh);
    h = pack_bf16(ah, bh);
    l = pack_bf16(__float2bfloat16_rn(ar), __float2bfloat16_rn(br));
}

__device__ __forceinline__ void ldmatrix_x4(uint32_t& r0, uint32_t& r1,
                                            uint32_t& r2, uint32_t& r3,
                                            uint32_t addr) {
    asm volatile("ldmatrix.sync.aligned.m8n8.x4.shared.b16 {%0,%1,%2,%3}, [%4];"
                 : "=r"(r0), "=r"(r1), "=r"(r2), "=r"(r3) : "r"(addr));
}

__device__ __forceinline__ void ldmatrix_x2(uint32_t& r0, uint32_t& r1,
                                            uint32_t addr) {
    asm volatile("ldmatrix.sync.aligned.m8n8.x2.shared.b16 {%0,%1}, [%2];"
                 : "=r"(r0), "=r"(r1) : "r"(addr));
}

__device__ __forceinline__ void mma_16816(float* d, const uint32_t* a,
                                          const uint32_t* b) {
    asm volatile(
        "mma.sync.aligned.m16n8k16.row.col.f32.bf16.bf16.f32 "
        "{%0,%1,%2,%3}, {%4,%5,%6,%7}, {%8,%9}, {%0,%1,%2,%3};"
        : "+f"(d[0]), "+f"(d[1]), "+f"(d[2]), "+f"(d[3])
        : "r"(a[0]), "r"(a[1]), "r"(a[2]), "r"(a[3]), "r"(b[0]), "r"(b[1]));
}

__global__ void __launch_bounds__(256, 2)
so3_linear_kernel(const float* __restrict__ x,      // [B, M, IN]
                  const float* __restrict__ w,      // [7, OUT, IN]
                  const float* __restrict__ bias,   // [OUT]
                  float* __restrict__ out)          // [B, M, OUT]
{
    extern __shared__ char smem[];
    const uint32_t sbase = smem_u32(smem);
    const int tid  = threadIdx.x;
    const int wid  = tid >> 5;
    const int lane = tid & 31;

    const int m  = (int)blockIdx.y;
    const int b0 = (int)blockIdx.x * TB;

    // l(m): largest l with l*l <= m
    int l = 0;
    while ((l + 1) * (l + 1) <= m) ++l;

    // ---- Load + split W[l] (128x128 f32 -> Wh/Wl bf16, pitch 136) ----
    {
        const float* wl = w + (size_t)l * OUT_DIM * IN_DIM;
        #pragma unroll
        for (int it = 0; it < 8; it++) {
            int idx = tid + it * 256;                 // 0 .. 2047
            int row = idx >> 4;                       // o (N dim)
            int ck  = idx & 15;                       // 8-float chunk along K
            const float4* p = (const float4*)(wl + (size_t)row * IN_DIM + ck * 8);
            float4 v0 = p[0], v1 = p[1];
            uint32_t h[4], lo[4];
            split2(v0.x, v0.y, h[0], lo[0]);
            split2(v0.z, v0.w, h[1], lo[1]);
            split2(v1.x, v1.y, h[2], lo[2]);
            split2(v1.z, v1.w, h[3], lo[3]);
            uint32_t off = ((uint32_t)row * PITCH + (uint32_t)ck * 8) * 2;
            *(uint4*)(smem + SMEM_WH + off) = make_uint4(h[0], h[1], h[2], h[3]);
            *(uint4*)(smem + SMEM_WL + off) = make_uint4(lo[0], lo[1], lo[2], lo[3]);
        }
    }

    // ---- Load + split X tile (TB rows, strided by M*IN) ----
    #pragma unroll
    for (int it = 0; it < 4; it++) {
        int idx = tid + it * 256;                     // 0 .. 1023
        int row = idx >> 4;
        int ck  = idx & 15;
        int b = b0 + row;
        float4 v0 = make_float4(0.f, 0.f, 0.f, 0.f), v1 = v0;
        if (b < B_TOTAL) {
            const float4* p =
                (const float4*)(x + ((size_t)b * M_TOTAL + m) * IN_DIM + ck * 8);
            v0 = p[0]; v1 = p[1];
        }
        uint32_t h[4], lo[4];
        split2(v0.x, v0.y, h[0], lo[0]);
        split2(v0.z, v0.w, h[1], lo[1]);
        split2(v1.x, v1.y, h[2], lo[2]);
        split2(v1.z, v1.w, h[3], lo[3]);
        uint32_t off = ((uint32_t)row * PITCH + (uint32_t)ck * 8) * 2;
        *(uint4*)(smem + SMEM_XH + off) = make_uint4(h[0], h[1], h[2], h[3]);
        *(uint4*)(smem + SMEM_XL + off) = make_uint4(lo[0], lo[1], lo[2], lo[3]);
    }
    __syncthreads();

    // ---- Warp tiling: 2 (m) x 4 (n) warps, each owns 32x32 output ----
    const int mrow = (wid >> 2) * 32;                 // 0 or 32
    const int ncol = (wid & 3) * 32;                  // 0,32,64,96

    // ldmatrix lane->address components
    const int ag = lane >> 3;                         // A: matrix index 0..3
    const int ar = (lane & 7) + ((ag & 1) << 3);      // A: row within 16
    const int ac = (ag >> 1) << 3;                    // A: col 0 or 8
    const int l16 = lane & 15;                        // B: lanes 0..15 give addrs
    const int br  = l16 & 7;                          // B: row (n) within 8
    const int bc  = (l16 >> 3) << 3;                  // B: col 0 or 8

    float acc[2][4][4];
    #pragma unroll
    for (int mt = 0; mt < 2; mt++)
        #pragma unroll
        for (int nt = 0; nt < 4; nt++)
            #pragma unroll
            for (int i = 0; i < 4; i++) acc[mt][nt][i] = 0.f;

    #pragma unroll
    for (int pass = 0; pass < 3; pass++) {
        const uint32_t abase = sbase + ((pass == 2) ? SMEM_XL : SMEM_XH);
        const uint32_t bbase = sbase + ((pass == 1) ? SMEM_WL : SMEM_WH);
        #pragma unroll
        for (int k = 0; k < 8; k++) {
            const int k0 = k * 16;
            uint32_t a[2][4], bfr[4][2];
            #pragma unroll
            for (int mt = 0; mt < 2; mt++) {
                uint32_t addr = abase +
                    (((uint32_t)(mrow + mt * 16 + ar) * PITCH +
                      (uint32_t)(k0 + ac)) * 2);
                ldmatrix_x4(a[mt][0], a[mt][1], a[mt][2], a[mt][3], addr);
            }
            #pragma unroll
            for (int nt = 0; nt < 4; nt++) {
                uint32_t addr = bbase +
                    (((uint32_t)(ncol + nt * 8 + br) * PITCH +
                      (uint32_t)(k0 + bc)) * 2);
                ldmatrix_x2(bfr[nt][0], bfr[nt][1], addr);
            }
            #pragma unroll
            for (int mt = 0; mt < 2; mt++)
                #pragma unroll
                for (int nt = 0; nt < 4; nt++)
                    mma_16816(acc[mt][nt], a[mt], bfr[nt]);
        }
    }

    // ---- Epilogue: write accumulators to global (+bias on m==0) ----
    {
        const int r  = lane >> 2;                     // 0..7
        const int c2 = (lane & 3) * 2;                // 0,2,4,6
        #pragma unroll
        for (int mt = 0; mt < 2; mt++) {
            #pragma unroll
            for (int half = 0; half < 2; half++) {    // rows r and r+8
                int row = mrow + mt * 16 + r + half * 8;
                int b = b0 + row;
                if (b >= B_TOTAL) continue;
                float* orow = out + ((size_t)b * M_TOTAL + m) * OUT_DIM;
                #pragma unroll
                for (int nt = 0; nt < 4; nt++) {
                    int col = ncol + nt * 8 + c2;
                    float v0 = acc[mt][nt][half * 2 + 0];
                    float v1 = acc[mt][nt][half * 2 + 1];
                    if (m == 0) {
                        v0 += bias[col];
                        v1 += bias[col + 1];
                    }
                    *(float2*)(orow + col) = make_float2(v0, v1);
                }
            }
        }
    }
}

extern "C" void kernel_launch(void* const* d_in, const int* in_sizes, int n_in,
                              void* d_out, int out_size) {
    const float* x    = (const float*)d_in[0];   // [20000, 49, 128] f32
    const float* w    = (const float*)d_in[1];   // [7, 128, 128] f32
    const float* bias = (const float*)d_in[2];   // [128] f32
    // d_in[3] = expand_index (int64) — l(m) computed in-kernel instead.
    float* out = (float*)d_out;

    cudaFuncSetAttribute(so3_linear_kernel,
                         cudaFuncAttributeMaxDynamicSharedMemorySize, SMEM_TOTAL);

    dim3 grid(NB_TILES, M_TOTAL);
    so3_linear_kernel<<<grid, 256, SMEM_TOTAL>>>(x, w, bias, out);
}

// round 9
// speedup vs baseline: 1.2981x; 1.2981x over previous
#include <cuda_runtime.h>
#include <cuda_bf16.h>
#include <cstdint>

// ---------------------------------------------------------------------------
// SO3_Linear: out[b,m,o] = sum_i x[b,m,i] * W[l(m)][o][i]  (+ bias on m==0)
// B=20000, M=49, IN=OUT=128, LMAX=6 (7 weights)
//
// sm_103 BASE target (no tcgen05/TMA in this toolchain): warp-level
// mma.sync.m16n8k16 bf16, fp32 accum, 3-term bf16 compensation
//   acc = Xh*Wh + Xh*Wl + Xl*Wh   (rel err ~2^-16)
// FUSED into a single k-loop so Ah/Al/Bh/Bl fragments are loaded once and
// reused by 24 MMAs per k-step (-33% LDS bytes, 3x issue density).
// Each CTA processes NTILE b-tiles so the W load+split is amortized.
// ---------------------------------------------------------------------------

#define B_TOTAL   20000
#define M_TOTAL   49
#define IN_DIM    128
#define OUT_DIM   128
#define TB        64                              // batch rows per tile
#define NXTILES   ((B_TOTAL + TB - 1) / TB)       // 313
#define NTILE     4                               // b-tiles per CTA
#define NB_CTAS   ((NXTILES + NTILE - 1) / NTILE) // 79

#define PITCH     136                             // bf16 elems per smem row (272 B)

// SMEM byte offsets (all 16B aligned)
#define SMEM_XH   0
#define SMEM_XL   (SMEM_XH + TB * PITCH * 2)          // 17408
#define SMEM_WH   (SMEM_XL + TB * PITCH * 2)          // 34816
#define SMEM_WL   (SMEM_WH + OUT_DIM * PITCH * 2)     // 69632
#define SMEM_TOTAL (SMEM_WL + OUT_DIM * PITCH * 2)    // 104448

__device__ __forceinline__ uint32_t smem_u32(const void* p) {
    uint32_t a;
    asm("{ .reg .u64 t; cvta.to.shared.u64 t, %1; cvt.u32.u64 %0, t; }"
        : "=r"(a) : "l"(p));
    return a;
}

__device__ __forceinline__ uint32_t pack_bf16(__nv_bfloat16 a, __nv_bfloat16 b) {
    return (uint32_t)__bfloat16_as_ushort(a) | ((uint32_t)__bfloat16_as_ushort(b) << 16);
}

// Split two fp32 into (hi, lo) bf16x2 pairs: v = hi + lo + O(2^-17 |v|)
__device__ __forceinline__ void split2(float a, float b, uint32_t& h, uint32_t& l) {
    __nv_bfloat16 ah = __float2bfloat16_rn(a);
    __nv_bfloat16 bh = __float2bfloat16_rn(b);
    float ar = a - __bfloat162float(ah);
    float br = b - __bfloat162float(bh);
    h = pack_bf16(ah, bh);
    l = pack_bf16(__float2bfloat16_rn(ar), __float2bfloat16_rn(br));
}

__device__ __forceinline__ void ldmatrix_x4(uint32_t& r0, uint32_t& r1,
                                            uint32_t& r2, uint32_t& r3,
                                            uint32_t addr) {
    asm volatile("ldmatrix.sync.aligned.m8n8.x4.shared.b16 {%0,%1,%2,%3}, [%4];"
                 : "=r"(r0), "=r"(r1), "=r"(r2), "=r"(r3) : "r"(addr));
}

__device__ __forceinline__ void mma_16816(float* d, const uint32_t* a,
                                          const uint32_t* b) {
    asm volatile(
        "mma.sync.aligned.m16n8k16.row.col.f32.bf16.bf16.f32 "
        "{%0,%1,%2,%3}, {%4,%5,%6,%7}, {%8,%9}, {%0,%1,%2,%3};"
        : "+f"(d[0]), "+f"(d[1]), "+f"(d[2]), "+f"(d[3])
        : "r"(a[0]), "r"(a[1]), "r"(a[2]), "r"(a[3]), "r"(b[0]), "r"(b[1]));
}

__global__ void __launch_bounds__(256, 2)
so3_linear_kernel(const float* __restrict__ x,      // [B, M, IN]
                  const float* __restrict__ w,      // [7, OUT, IN]
                  const float* __restrict__ bias,   // [OUT]
                  float* __restrict__ out)          // [B, M, OUT]
{
    extern __shared__ char smem[];
    const uint32_t sbase = smem_u32(smem);
    const int tid  = threadIdx.x;
    const int wid  = tid >> 5;
    const int lane = tid & 31;

    const int m = (int)blockIdx.y;

    // l(m): largest l with l*l <= m
    int l = 0;
    while ((l + 1) * (l + 1) <= m) ++l;

    // ---- Load + split W[l] once (128x128 f32 -> Wh/Wl bf16, pitch 136) ----
    {
        const float* wl = w + (size_t)l * OUT_DIM * IN_DIM;
        #pragma unroll
        for (int it = 0; it < 8; it++) {
            int idx = tid + it * 256;                 // 0 .. 2047
            int row = idx >> 4;                       // o (N dim)
            int ck  = idx & 15;                       // 8-float chunk along K
            const float4* p = (const float4*)(wl + (size_t)row * IN_DIM + ck * 8);
            float4 v0 = p[0], v1 = p[1];
            uint32_t h[4], lo[4];
            split2(v0.x, v0.y, h[0], lo[0]);
            split2(v0.z, v0.w, h[1], lo[1]);
            split2(v1.x, v1.y, h[2], lo[2]);
            split2(v1.z, v1.w, h[3], lo[3]);
            uint32_t off = ((uint32_t)row * PITCH + (uint32_t)ck * 8) * 2;
            *(uint4*)(smem + SMEM_WH + off) = make_uint4(h[0], h[1], h[2], h[3]);
            *(uint4*)(smem + SMEM_WL + off) = make_uint4(lo[0], lo[1], lo[2], lo[3]);
        }
    }

    // ---- Warp tiling: 2 (m) x 4 (n) warps, each owns 32x32 output ----
    const int mrow = (wid >> 2) * 32;                 // 0 or 32
    const int ncol = (wid & 3) * 32;                  // 0,32,64,96

    // ldmatrix lane->address components
    const int ag = lane >> 3;                         // A: matrix index 0..3
    const int ar = (lane & 7) + ((ag & 1) << 3);      // A: row within 16
    const int ac = (ag >> 1) << 3;                    // A: col 0 or 8
    // B x4: group g=lane>>3 -> matrix (n-half g>>1, k-half g&1)
    const int bn = ((lane >> 4) << 3) + (lane & 7);   // n-row within 16
    const int bk = ((lane >> 3) & 1) << 3;            // k col 0 or 8

    // X-load lane mapping
    const int xrow = tid >> 2;                        // 0..63
    const int xck  = (tid & 3) * 4;                   // chunk-of-8 pairs: 0,4,8,12

    for (int t = 0; t < NTILE; t++) {
        const int tile = (int)blockIdx.x * NTILE + t;
        if (tile >= NXTILES) break;
        const int b0 = tile * TB;

        // ---- Issue X global loads into registers (overlaps prior MMA tail) --
        // thread loads 4 chunks of 8 floats: row = tid>>2, ck = (tid&3)*4 + j
        float4 v[4][2];
        {
            const int b = b0 + xrow;
            const bool valid = (b < B_TOTAL);
            const float4* p =
                (const float4*)(x + ((size_t)b * M_TOTAL + m) * IN_DIM);
            #pragma unroll
            for (int j = 0; j < 4; j++) {
                if (valid) {
                    v[j][0] = p[(xck + j) * 2];
                    v[j][1] = p[(xck + j) * 2 + 1];
                } else {
                    v[j][0] = make_float4(0.f, 0.f, 0.f, 0.f);
                    v[j][1] = v[j][0];
                }
            }
        }

        __syncthreads();   // previous tile's MMA reads of X smem complete

        // ---- Split + store X tile ----
        #pragma unroll
        for (int j = 0; j < 4; j++) {
            uint32_t h[4], lo[4];
            split2(v[j][0].x, v[j][0].y, h[0], lo[0]);
            split2(v[j][0].z, v[j][0].w, h[1], lo[1]);
            split2(v[j][1].x, v[j][1].y, h[2], lo[2]);
            split2(v[j][1].z, v[j][1].w, h[3], lo[3]);
            uint32_t off = ((uint32_t)xrow * PITCH + (uint32_t)(xck + j) * 8) * 2;
            *(uint4*)(smem + SMEM_XH + off) = make_uint4(h[0], h[1], h[2], h[3]);
            *(uint4*)(smem + SMEM_XL + off) = make_uint4(lo[0], lo[1], lo[2], lo[3]);
        }
        __syncthreads();   // X (and W on first tile) visible to all warps

        // ---- Fused 3-term MMA loop ----
        float acc[2][4][4];
        #pragma unroll
        for (int mt = 0; mt < 2; mt++)
            #pragma unroll
            for (int nt = 0; nt < 4; nt++)
                #pragma unroll
                for (int i = 0; i < 4; i++) acc[mt][nt][i] = 0.f;

        #pragma unroll
        for (int k = 0; k < 8; k++) {
            const int k0 = k * 16;
            uint32_t ah[2][4], al[2][4], bh[4][2], bl[4][2];

            #pragma unroll
            for (int mt = 0; mt < 2; mt++) {
                uint32_t aoff = (((uint32_t)(mrow + mt * 16 + ar)) * PITCH +
                                 (uint32_t)(k0 + ac)) * 2;
                ldmatrix_x4(ah[mt][0], ah[mt][1], ah[mt][2], ah[mt][3],
                            sbase + SMEM_XH + aoff);
                ldmatrix_x4(al[mt][0], al[mt][1], al[mt][2], al[mt][3],
                            sbase + SMEM_XL + aoff);
            }
            #pragma unroll
            for (int np = 0; np < 2; np++) {
                uint32_t boff = (((uint32_t)(ncol + np * 16 + bn)) * PITCH +
                                 (uint32_t)(k0 + bk)) * 2;
                uint32_t r0, r1, r2, r3;
                ldmatrix_x4(r0, r1, r2, r3, sbase + SMEM_WH + boff);
                bh[2 * np][0] = r0; bh[2 * np][1] = r1;
                bh[2 * np + 1][0] = r2; bh[2 * np + 1][1] = r3;
                ldmatrix_x4(r0, r1, r2, r3, sbase + SMEM_WL + boff);
                bl[2 * np][0] = r0; bl[2 * np][1] = r1;
                bl[2 * np + 1][0] = r2; bl[2 * np + 1][1] = r3;
            }

            #pragma unroll
            for (int mt = 0; mt < 2; mt++)
                #pragma unroll
                for (int nt = 0; nt < 4; nt++)
                    mma_16816(acc[mt][nt], ah[mt], bh[nt]);
            #pragma unroll
            for (int mt = 0; mt < 2; mt++)
                #pragma unroll
                for (int nt = 0; nt < 4; nt++)
                    mma_16816(acc[mt][nt], ah[mt], bl[nt]);
            #pragma unroll
            for (int mt = 0; mt < 2; mt++)
                #pragma unroll
                for (int nt = 0; nt < 4; nt++)
                    mma_16816(acc[mt][nt], al[mt], bh[nt]);
        }

        // ---- Epilogue: write accumulators to global (+bias on m==0) ----
        {
            const int r  = lane >> 2;                 // 0..7
            const int c2 = (lane & 3) * 2;            // 0,2,4,6
            #pragma unroll
            for (int mt = 0; mt < 2; mt++) {
                #pragma unroll
                for (int half = 0; half < 2; half++) {  // rows r and r+8
                    int row = mrow + mt * 16 + r + half * 8;
                    int b = b0 + row;
                    if (b >= B_TOTAL) continue;
                    float* orow = out + ((size_t)b * M_TOTAL + m) * OUT_DIM;
                    #pragma unroll
                    for (int nt = 0; nt < 4; nt++) {
                        int col = ncol + nt * 8 + c2;
                        float v0 = acc[mt][nt][half * 2 + 0];
                        float v1 = acc[mt][nt][half * 2 + 1];
                        if (m == 0) {
                            v0 += bias[col];
                            v1 += bias[col + 1];
                        }
                        *(float2*)(orow + col) = make_float2(v0, v1);
                    }
                }
            }
        }
    }
}

extern "C" void kernel_launch(void* const* d_in, const int* in_sizes, int n_in,
                              void* d_out, int out_size) {
    const float* x    = (const float*)d_in[0];   // [20000, 49, 128] f32
    const float* w    = (const float*)d_in[1];   // [7, 128, 128] f32
    const float* bias = (const float*)d_in[2];   // [128] f32
    // d_in[3] = expand_index (int64) — l(m) computed in-kernel instead.
    float* out = (float*)d_out;

    cudaFuncSetAttribute(so3_linear_kernel,
                         cudaFuncAttributeMaxDynamicSharedMemorySize, SMEM_TOTAL);

    dim3 grid(NB_CTAS, M_TOTAL);
    so3_linear_kernel<<<grid, 256, SMEM_TOTAL>>>(x, w, bias, out);
}

// round 12
// speedup vs baseline: 1.8687x; 1.4396x over previous
#include <cuda_runtime.h>
#include <cuda_fp16.h>
#include <cstdint>

// ---------------------------------------------------------------------------
// SO3_Linear: out[b,m,o] = sum_i x[b,m,i] * W[l(m)][o][i]  (+ bias on m==0)
// B=20000, M=49, IN=OUT=128, LMAX=6 (7 weights)
//
// sm_103 BASE target: warp-level mma.sync.m16n8k16 f16 with fp32 accum.
// fp16 TWO-term compensation:  acc = Xh*Wh + Xl*Wh   (= (xh+xl)*wh)
// where x = xh + xl (fp16 split, residual ~2^-12|x|) and wh = fp16(w).
// Dropped term x*wl gives rel L2 err ~2.2e-4 << 1e-3 threshold.
// 4 warps/CTA, warp tile 32x64, CTA tile 64x128, 3 CTAs/SM resident.
// ---------------------------------------------------------------------------

#define B_TOTAL   20000
#define M_TOTAL   49
#define IN_DIM    128
#define OUT_DIM   128
#define TB        64                              // batch rows per tile
#define NXTILES   ((B_TOTAL + TB - 1) / TB)       // 313
#define NTILE     4                               // b-tiles per CTA
#define NB_CTAS   ((NXTILES + NTILE - 1) / NTILE) // 79
#define NTHREADS  128

#define PITCH     136                             // fp16 elems per smem row (272 B)

// SMEM byte offsets (all 16B aligned)
#define SMEM_XH   0
#define SMEM_XL   (SMEM_XH + TB * PITCH * 2)          // 17408
#define SMEM_WH   (SMEM_XL + TB * PITCH * 2)          // 34816
#define SMEM_TOTAL (SMEM_WH + OUT_DIM * PITCH * 2)    // 69632

__device__ __forceinline__ uint32_t smem_u32(const void* p) {
    uint32_t a;
    asm("{ .reg .u64 t; cvta.to.shared.u64 t, %1; cvt.u32.u64 %0, t; }"
        : "=r"(a) : "l"(p));
    return a;
}

__device__ __forceinline__ uint32_t pack_h2(__half a, __half b) {
    return (uint32_t)__half_as_ushort(a) | ((uint32_t)__half_as_ushort(b) << 16);
}

// Split two fp32 into (hi, lo) fp16x2 pairs: v = hi + lo + O(2^-23 |v|)
__device__ __forceinline__ void split2h(float a, float b, uint32_t& h, uint32_t& l) {
    __half ah = __float2half_rn(a);
    __half bh = __float2half_rn(b);
    float ar = a - __half2float(ah);
    float br = b - __half2float(bh);
    h = pack_h2(ah, bh);
    l = pack_h2(__float2half_rn(ar), __float2half_rn(br));
}

__device__ __forceinline__ uint32_t cvt2h(float a, float b) {
    return pack_h2(__float2half_rn(a), __float2half_rn(b));
}

__device__ __forceinline__ void ldmatrix_x4(uint32_t& r0, uint32_t& r1,
                                            uint32_t& r2, uint32_t& r3,
                                            uint32_t addr) {
    asm volatile("ldmatrix.sync.aligned.m8n8.x4.shared.b16 {%0,%1,%2,%3}, [%4];"
                 : "=r"(r0), "=r"(r1), "=r"(r2), "=r"(r3) : "r"(addr));
}

__device__ __forceinline__ void mma_16816(float* d, const uint32_t* a,
                                          const uint32_t* b) {
    asm volatile(
        "mma.sync.aligned.m16n8k16.row.col.f32.f16.f16.f32 "
        "{%0,%1,%2,%3}, {%4,%5,%6,%7}, {%8,%9}, {%0,%1,%2,%3};"
        : "+f"(d[0]), "+f"(d[1]), "+f"(d[2]), "+f"(d[3])
        : "r"(a[0]), "r"(a[1]), "r"(a[2]), "r"(a[3]), "r"(b[0]), "r"(b[1]));
}

__global__ void __launch_bounds__(NTHREADS, 3)
so3_linear_kernel(const float* __restrict__ x,      // [B, M, IN]
                  const float* __restrict__ w,      // [7, OUT, IN]
                  const float* __restrict__ bias,   // [OUT]
                  float* __restrict__ out)          // [B, M, OUT]
{
    extern __shared__ char smem[];
    const uint32_t sbase = smem_u32(smem);
    const int tid  = threadIdx.x;
    const int wid  = tid >> 5;
    const int lane = tid & 31;

    const int m = (int)blockIdx.y;

    // l(m): largest l with l*l <= m
    int l = 0;
    while ((l + 1) * (l + 1) <= m) ++l;

    // ---- Convert W[l] once (128x128 f32 -> fp16 Wh, pitch 136) ----
    {
        const float* wl = w + (size_t)l * OUT_DIM * IN_DIM;
        #pragma unroll
        for (int it = 0; it < 16; it++) {
            int idx = tid + it * NTHREADS;            // 0 .. 2047
            int row = idx >> 4;                       // o (N dim)
            int ck  = idx & 15;                       // 8-float chunk along K
            const float4* p = (const float4*)(wl + (size_t)row * IN_DIM + ck * 8);
            float4 v0 = p[0], v1 = p[1];
            uint4 hv = make_uint4(cvt2h(v0.x, v0.y), cvt2h(v0.z, v0.w),
                                  cvt2h(v1.x, v1.y), cvt2h(v1.z, v1.w));
            uint32_t off = ((uint32_t)row * PITCH + (uint32_t)ck * 8) * 2;
            *(uint4*)(smem + SMEM_WH + off) = hv;
        }
    }

    // ---- Warp tiling: 2 (m) x 2 (n) warps, each owns 32x64 output ----
    const int mrow = (wid >> 1) * 32;                 // 0 or 32
    const int ncol = (wid & 1) * 64;                  // 0 or 64

    // ldmatrix lane->address components
    const int ag = lane >> 3;                         // A: matrix index 0..3
    const int ar = (lane & 7) + ((ag & 1) << 3);      // A: row within 16
    const int ac = (ag >> 1) << 3;                    // A: col 0 or 8
    // B x4: group g=lane>>3 -> matrix (n-half g>>1, k-half g&1)
    const int bn = ((lane >> 4) << 3) + (lane & 7);   // n-row within 16
    const int bk = ((lane >> 3) & 1) << 3;            // k col 0 or 8

    for (int t = 0; t < NTILE; t++) {
        const int tile = (int)blockIdx.x * NTILE + t;
        if (tile >= NXTILES) break;
        const int b0 = tile * TB;

        __syncthreads();   // previous tile's MMA reads of X smem complete

        // ---- Load + split X tile (64 rows x 128) ----
        #pragma unroll
        for (int it = 0; it < 8; it++) {
            int idx = tid + it * NTHREADS;            // 0 .. 1023
            int row = idx >> 4;
            int ck  = idx & 15;
            int b = b0 + row;
            float4 v0 = make_float4(0.f, 0.f, 0.f, 0.f), v1 = v0;
            if (b < B_TOTAL) {
                const float4* p =
                    (const float4*)(x + ((size_t)b * M_TOTAL + m) * IN_DIM + ck * 8);
                v0 = p[0]; v1 = p[1];
            }
            uint32_t h[4], lo[4];
            split2h(v0.x, v0.y, h[0], lo[0]);
            split2h(v0.z, v0.w, h[1], lo[1]);
            split2h(v1.x, v1.y, h[2], lo[2]);
            split2h(v1.z, v1.w, h[3], lo[3]);
            uint32_t off = ((uint32_t)row * PITCH + (uint32_t)ck * 8) * 2;
            *(uint4*)(smem + SMEM_XH + off) = make_uint4(h[0], h[1], h[2], h[3]);
            *(uint4*)(smem + SMEM_XL + off) = make_uint4(lo[0], lo[1], lo[2], lo[3]);
        }
        __syncthreads();   // X (and W on first tile) visible to all warps

        // ---- Fused 2-term MMA loop: acc = Xh*Wh + Xl*Wh ----
        float acc[2][8][4];
        #pragma unroll
        for (int mt = 0; mt < 2; mt++)
            #pragma unroll
            for (int nt = 0; nt < 8; nt++)
                #pragma unroll
                for (int i = 0; i < 4; i++) acc[mt][nt][i] = 0.f;

        #pragma unroll
        for (int k = 0; k < 8; k++) {
            const int k0 = k * 16;
            uint32_t ah[2][4], al[2][4], bh[8][2];

            #pragma unroll
            for (int mt = 0; mt < 2; mt++) {
                uint32_t aoff = (((uint32_t)(mrow + mt * 16 + ar)) * PITCH +
                                 (uint32_t)(k0 + ac)) * 2;
                ldmatrix_x4(ah[mt][0], ah[mt][1], ah[mt][2], ah[mt][3],
                            sbase + SMEM_XH + aoff);
                ldmatrix_x4(al[mt][0], al[mt][1], al[mt][2], al[mt][3],
                            sbase + SMEM_XL + aoff);
            }
            #pragma unroll
            for (int np = 0; np < 4; np++) {
                uint32_t boff = (((uint32_t)(ncol + np * 16 + bn)) * PITCH +
                                 (uint32_t)(k0 + bk)) * 2;
                uint32_t r0, r1, r2, r3;
                ldmatrix_x4(r0, r1, r2, r3, sbase + SMEM_WH + boff);
                bh[2 * np][0] = r0;     bh[2 * np][1] = r1;
                bh[2 * np + 1][0] = r2; bh[2 * np + 1][1] = r3;
            }

            #pragma unroll
            for (int mt = 0; mt < 2; mt++)
                #pragma unroll
                for (int nt = 0; nt < 8; nt++)
                    mma_16816(acc[mt][nt], ah[mt], bh[nt]);
            #pragma unroll
            for (int mt = 0; mt < 2; mt++)
                #pragma unroll
                for (int nt = 0; nt < 8; nt++)
                    mma_16816(acc[mt][nt], al[mt], bh[nt]);
        }

        // ---- Epilogue: write accumulators to global (+bias on m==0) ----
        {
            const int r  = lane >> 2;                 // 0..7
            const int c2 = (lane & 3) * 2;            // 0,2,4,6
            #pragma unroll
            for (int mt = 0; mt < 2; mt++) {
                #pragma unroll
                for (int half = 0; half < 2; half++) {  // rows r and r+8
                    int row = mrow + mt * 16 + r + half * 8;
                    int b = b0 + row;
                    if (b >= B_TOTAL) continue;
                    float* orow = out + ((size_t)b * M_TOTAL + m) * OUT_DIM;
                    #pragma unroll
                    for (int nt = 0; nt < 8; nt++) {
                        int col = ncol + nt * 8 + c2;
                        float v0 = acc[mt][nt][half * 2 + 0];
                        float v1 = acc[mt][nt][half * 2 + 1];
                        if (m == 0) {
                            v0 += bias[col];
                            v1 += bias[col + 1];
                        }
                        *(float2*)(orow + col) = make_float2(v0, v1);
                    }
                }
            }
        }
    }
}

extern "C" void kernel_launch(void* const* d_in, const int* in_sizes, int n_in,
                              void* d_out, int out_size) {
    const float* x    = (const float*)d_in[0];   // [20000, 49, 128] f32
    const float* w    = (const float*)d_in[1];   // [7, 128, 128] f32
    const float* bias = (const float*)d_in[2];   // [128] f32
    // d_in[3] = expand_index (int64) — l(m) computed in-kernel instead.
    float* out = (float*)d_out;

    cudaFuncSetAttribute(so3_linear_kernel,
                         cudaFuncAttributeMaxDynamicSharedMemorySize, SMEM_TOTAL);

    dim3 grid(NB_CTAS, M_TOTAL);
    so3_linear_kernel<<<grid, NTHREADS, SMEM_TOTAL>>>(x, w, bias, out);
}